// round 8
// baseline (speedup 1.0000x reference)
#include <cuda_runtime.h>
#include <cuda_bf16.h>
#include <cstdint>
#include <math.h>

#define NPTS 65536
#define GD   64
#define G3   (GD*GD*GD)
#define KNN  12
#define NETB 296            // k_net grid: 2 blocks/SM x 148 SMs, all resident

typedef __nv_bfloat16 bf16;

// ================= mma.sync helpers =================
__device__ __forceinline__ uint32_t smem_to_u32(const void* p){
    uint32_t a;
    asm("{ .reg .u64 t; cvta.to.shared.u64 t, %1; cvt.u32.u64 %0, t; }" : "=r"(a) : "l"(p));
    return a;
}
__device__ __forceinline__ void ldsm4(uint32_t& r0,uint32_t& r1,uint32_t& r2,uint32_t& r3,uint32_t addr){
    asm volatile("ldmatrix.sync.aligned.m8n8.x4.shared.b16 {%0,%1,%2,%3},[%4];"
        : "=r"(r0),"=r"(r1),"=r"(r2),"=r"(r3) : "r"(addr));
}
__device__ __forceinline__ void ldsm2(uint32_t& r0,uint32_t& r1,uint32_t addr){
    asm volatile("ldmatrix.sync.aligned.m8n8.x2.shared.b16 {%0,%1},[%2];"
        : "=r"(r0),"=r"(r1) : "r"(addr));
}
__device__ __forceinline__ void mma16816(float* c, const uint32_t* a, const uint32_t* b){
    asm volatile("mma.sync.aligned.m16n8k16.row.col.f32.bf16.bf16.f32 "
        "{%0,%1,%2,%3},{%4,%5,%6,%7},{%8,%9},{%0,%1,%2,%3};"
        : "+f"(c[0]),"+f"(c[1]),"+f"(c[2]),"+f"(c[3])
        : "r"(a[0]),"r"(a[1]),"r"(a[2]),"r"(a[3]), "r"(b[0]),"r"(b[1]));
}

// ================= scratch =================
__device__ float4   g_pts[NPTS];
__device__ float4   g_spts[NPTS];
__device__ int      g_sorted[NPTS];
__device__ int      g_knn[NPTS*KNN];
__device__ int      g_cellcount[G3];
__device__ int      g_cellstart[G3];
__device__ int2     g_cellrange[G3];
__device__ int      g_cellfill[G3];
__device__ int      g_cellof[NPTS];
__device__ unsigned g_bmin[3] = {0xFFFFFFFFu,0xFFFFFFFFu,0xFFFFFFFFu};
__device__ unsigned g_bmax[3] = {0u,0u,0u};
__device__ int      g_tsum[512];
__device__ unsigned g_barcnt;      // used by k_scan_scatter
__device__ unsigned g_barcnt2;     // used by k_net
__device__ float    g_film[7*512];
__device__ bf16     g_ffh[NPTS*64],  g_ffl[NPTS*64];
__device__ bf16     g_gah[NPTS*192], g_gal[NPTS*192];
__device__ bf16     g_gbh[NPTS*192], g_gbl[NPTS*192];
__device__ bf16     g_aggh[NPTS*192],g_aggl[NPTS*192];
__device__ bf16     g_hah[NPTS*256], g_hal[NPTS*256];
__device__ bf16     g_hbh[NPTS*256], g_hbl[NPTS*256];
__device__ float    g_h0[NPTS*256];
__device__ float    g_hf[NPTS*256];
__device__ bf16     g_Winh[64*256],   g_Winl[64*256];
__device__ bf16     g_Wginh[64*192],  g_Wginl[64*192];
__device__ bf16     g_Wsh[4*192*192], g_Wsl[4*192*192];
__device__ bf16     g_Wnh[4*192*192], g_Wnl[4*192*192];
__device__ bf16     g_Wgoh[192*256],  g_Wgol[192*256];
__device__ bf16     g_Wh[7*256*256],  g_Wl[7*256*256];

__device__ __forceinline__ unsigned fmap(float x){
    unsigned u = __float_as_uint(x);
    return (u & 0x80000000u) ? ~u : (u | 0x80000000u);
}
__device__ __forceinline__ float funmap(unsigned u){
    return (u & 0x80000000u) ? __uint_as_float(u & 0x7FFFFFFFu) : __uint_as_float(~u);
}
__device__ __forceinline__ void splt(float v, bf16* dh, bf16* dl, int i){
    bf16 h = __float2bfloat16(v);
    dh[i] = h;
    dl[i] = __float2bfloat16(v - __bfloat162float(h));
}

// ================= L1: init + prep + weight split + film =================
__global__ void k_init_prep(const float* __restrict__ x,
    const float* __restrict__ W_in, const float* __restrict__ Wg_in,
    const float* __restrict__ Ws, const float* __restrict__ Wn,
    const float* __restrict__ Wg_out, const float* __restrict__ W,
    const float* __restrict__ cond,
    const float* __restrict__ Wf_g, const float* __restrict__ bf_g,
    const float* __restrict__ Wf_b, const float* __restrict__ bf_b,
    const float* __restrict__ bmlp)
{
    int gid = blockIdx.x*256 + threadIdx.x;     // 524288 threads
    if (gid == 0){ g_barcnt = 0u; g_barcnt2 = 0u; }
    if (gid < G3){ g_cellcount[gid]=0; g_cellfill[gid]=0; }
    if (gid < NPTS){
        float x0=x[gid*3+0], x1=x[gid*3+1], x2=x[gid*3+2];
        g_pts[gid] = make_float4(x0,x1,x2, x0*x0+x1*x1+x2*x2);
        float mn0=x0, mn1=x1, mn2=x2, mx0=x0, mx1=x1, mx2=x2;
        #pragma unroll
        for (int o=16;o>0;o>>=1){
            mn0=fminf(mn0,__shfl_down_sync(0xffffffffu,mn0,o));
            mn1=fminf(mn1,__shfl_down_sync(0xffffffffu,mn1,o));
            mn2=fminf(mn2,__shfl_down_sync(0xffffffffu,mn2,o));
            mx0=fmaxf(mx0,__shfl_down_sync(0xffffffffu,mx0,o));
            mx1=fmaxf(mx1,__shfl_down_sync(0xffffffffu,mx1,o));
            mx2=fmaxf(mx2,__shfl_down_sync(0xffffffffu,mx2,o));
        }
        if ((threadIdx.x & 31) == 0){
            atomicMin(&g_bmin[0], fmap(mn0)); atomicMax(&g_bmax[0], fmap(mx0));
            atomicMin(&g_bmin[1], fmap(mn1)); atomicMax(&g_bmax[1], fmap(mx1));
            atomicMin(&g_bmin[2], fmap(mn2)); atomicMax(&g_bmax[2], fmap(mx2));
        }
    }
    for (int i=gid; i<7*256*256; i+=524288) splt(W[i], g_Wh, g_Wl, i);
    for (int i=gid; i<4*192*192; i+=524288){
        splt(Ws[i], g_Wsh, g_Wsl, i);
        splt(Wn[i], g_Wnh, g_Wnl, i);
    }
    for (int i=gid; i<192*256; i+=524288) splt(Wg_out[i], g_Wgoh, g_Wgol, i);
    for (int i=gid; i<64*256; i+=524288){
        int row=i>>8, col=i&255;
        splt(row<48 ? W_in[row*256+col] : 0.f, g_Winh, g_Winl, i);
    }
    for (int i=gid; i<64*192; i+=524288){
        int row=i/192, col=i-row*192;
        splt(row<48 ? Wg_in[row*192+col] : 0.f, g_Wginh, g_Wginl, i);
    }
    if (gid < 1792){
        int l = gid>>8, j = gid&255;
        float ga = bf_g[l*256+j], ba = bf_b[l*256+j];
        for (int k=0;k<64;k++){
            float cv = cond[k];
            ga = fmaf(cv, Wf_g[(l*64+k)*256+j], ga);
            ba = fmaf(cv, Wf_b[(l*64+k)*256+j], ba);
        }
        float g1 = 1.f + ga;
        g_film[l*512 + j]       = g1;
        g_film[l*512 + 256 + j] = fmaf(bmlp[l*256+j], g1, ba);
    }
}

// ================= L2: cell assignment =================
__global__ void k_cell(){
    int i = blockIdx.x*blockDim.x + threadIdx.x;
    float4 p = g_pts[i];
    float lo0=funmap(g_bmin[0]), lo1=funmap(g_bmin[1]), lo2=funmap(g_bmin[2]);
    float ih0 = (float)GD / (funmap(g_bmax[0]) - lo0);
    float ih1 = (float)GD / (funmap(g_bmax[1]) - lo1);
    float ih2 = (float)GD / (funmap(g_bmax[2]) - lo2);
    int cx = min(GD-1, max(0, (int)floorf((p.x - lo0)*ih0)));
    int cy = min(GD-1, max(0, (int)floorf((p.y - lo1)*ih1)));
    int cz = min(GD-1, max(0, (int)floorf((p.z - lo2)*ih2)));
    int c = (cz*GD + cy)*GD + cx;
    g_cellof[i] = c;
    atomicAdd(&g_cellcount[c], 1);
}

// ================= L3: fused scan + scatter (512 blocks all-resident) =================
__device__ __forceinline__ void gridbar(unsigned target){
    __syncthreads();
    __threadfence();
    if (threadIdx.x == 0){
        atomicAdd(&g_barcnt, 1u);
        while (atomicAdd(&g_barcnt, 0u) < target) { }
    }
    __syncthreads();
}

__global__ void __launch_bounds__(512,4) k_scan_scatter(){
    __shared__ int s[512];
    int bid = blockIdx.x, tid = threadIdx.x;
    int gid = bid*512 + tid;

    int v = g_cellcount[gid];
    s[tid] = v; __syncthreads();
    for (int off=1; off<512; off<<=1){
        int t = (tid >= off) ? s[tid-off] : 0;
        __syncthreads(); s[tid] += t; __syncthreads();
    }
    g_cellstart[gid] = s[tid] - v;
    if (tid == 511) g_tsum[bid] = s[511];
    gridbar(512);

    int part = 0;
    for (int j=tid; j<bid; j+=512) part += g_tsum[j];
    s[tid] = part; __syncthreads();
    for (int off=256; off>0; off>>=1){
        if (tid < off) s[tid] += s[tid+off];
        __syncthreads();
    }
    int offset = s[0];
    int st = g_cellstart[gid] + offset;
    g_cellstart[gid] = st;
    g_cellrange[gid] = make_int2(st, v);
    gridbar(1024);

    for (int t=tid; t<128; t+=512){
        int i = bid*128 + t;
        int c = g_cellof[i];
        int pos = g_cellstart[c] + atomicAdd(&g_cellfill[c], 1);
        g_sorted[pos] = i;
        g_spts[pos]  = g_pts[i];
    }
}

// ================= L4: fused network (all-resident, grid barriers) =================
#define F_BIAS 1
#define F_FILM 2
#define F_SILU 4
#define F_RES  8
#define F_F32  16
#define F_BF16 32

__device__ __forceinline__ void netbar(int gen){
    __syncthreads();
    __threadfence();
    if (threadIdx.x == 0){
        atomicAdd(&g_barcnt2, 1u);
        unsigned target = (unsigned)gen * (unsigned)gridDim.x;
        while (atomicAdd(&g_barcnt2, 0u) < target) { }
    }
    __syncthreads();
}

// one GEMM layer, block-strided over tiles (128 rows x 64 cols per tile)
__device__ void mma_layer(
    bf16 (*Ah)[40], bf16 (*Al)[40], bf16 (*Bh)[40], bf16 (*Bl)[40],
    const bf16* a1h, const bf16* a1l, const bf16* W1h, const bf16* W1l, int k1,
    const bf16* a2h, const bf16* a2l, const bf16* W2h, const bf16* W2l, int k2,
    int Mout, int gx,
    const float* bias, const float* gamma, const float* beta, const float* resi,
    float* outf, bf16* outh, bf16* outl, int flags)
{
    int tid = threadIdx.x, wid = tid>>5, lane = tid&31;
    int wm = wid & 3, wn = wid >> 2;

    uint32_t aAh = smem_to_u32(&Ah[wm*32 + (lane & 15)][(lane >> 4) * 8]);
    uint32_t aAl = smem_to_u32(&Al[wm*32 + (lane & 15)][(lane >> 4) * 8]);
    uint32_t aBh = smem_to_u32(&Bh[wn*32 + (lane & 7)][((lane >> 3) & 1) * 8]);
    uint32_t aBl = smem_to_u32(&Bl[wn*32 + (lane & 7)][((lane >> 3) & 1) * 8]);

    int ntiles = gx * 512;
    int nchunk = (k1 + k2) >> 5;

    for (int tile = blockIdx.x; tile < ntiles; tile += gridDim.x){
        int bx = tile % gx, by = tile / gx;
        int row0 = by*128, col0 = bx*64;
        __syncthreads();   // protect smem from previous tile's consumers

        float acc[2][4][4];
        #pragma unroll
        for (int mt=0;mt<2;mt++)
            #pragma unroll
            for (int nt=0;nt<4;nt++)
                #pragma unroll
                for (int e=0;e<4;e++) acc[mt][nt][e]=0.f;

        for (int c=0; c<nchunk; c++){
            int kg = c<<5;
            const bf16 *ah, *al, *Wph, *Wpl; int span, koff;
            if (kg < k1){ ah=a1h; al=a1l; Wph=W1h; Wpl=W1l; span=k1; koff=kg; }
            else        { ah=a2h; al=a2l; Wph=W2h; Wpl=W2l; span=k2; koff=kg-k1; }

            // A tiles (activations, written in-kernel -> L2 coherent loads)
            #pragma unroll
            for (int t=tid; t<1024; t+=256){
                int r = t>>3, g = (t&7)*4;
                size_t s = (size_t)(row0+r)*span + koff + g;
                uint2 vh = __ldcg((const uint2*)(ah + s));
                uint2 vl = __ldcg((const uint2*)(al + s));
                *(uint2*)&Ah[r][g] = vh;
                *(uint2*)&Al[r][g] = vl;
            }
            // B tiles (weights, pre-split in earlier launch -> normal loads)
            {
                int n8 = (tid & 7) * 8, kk = tid >> 3;
                size_t s = (size_t)(koff+kk)*Mout + col0 + n8;
                uint4 vh = *(const uint4*)(Wph + s);
                uint4 vl = *(const uint4*)(Wpl + s);
                const bf16* ph = (const bf16*)&vh;
                const bf16* pl = (const bf16*)&vl;
                #pragma unroll
                for (int j2=0;j2<8;j2++){ Bh[n8+j2][kk]=ph[j2]; Bl[n8+j2][kk]=pl[j2]; }
            }
            __syncthreads();

            #pragma unroll
            for (int ks=0; ks<2; ks++){
                uint32_t afh[2][4], afl[2][4], bfh[4][2], bfl[4][2];
                #pragma unroll
                for (int mt=0; mt<2; mt++){
                    uint32_t off = (mt*16*40 + ks*16) * 2;
                    ldsm4(afh[mt][0],afh[mt][1],afh[mt][2],afh[mt][3], aAh + off);
                    ldsm4(afl[mt][0],afl[mt][1],afl[mt][2],afl[mt][3], aAl + off);
                }
                #pragma unroll
                for (int nt=0; nt<4; nt++){
                    uint32_t off = (nt*8*40 + ks*16) * 2;
                    ldsm2(bfh[nt][0],bfh[nt][1], aBh + off);
                    ldsm2(bfl[nt][0],bfl[nt][1], aBl + off);
                }
                #pragma unroll
                for (int mt=0; mt<2; mt++)
                    #pragma unroll
                    for (int nt=0; nt<4; nt++){
                        mma16816(acc[mt][nt], afh[mt], bfh[nt]);
                        mma16816(acc[mt][nt], afh[mt], bfl[nt]);
                        mma16816(acc[mt][nt], afl[mt], bfh[nt]);
                    }
            }
            __syncthreads();
        }

        #pragma unroll
        for (int mt=0; mt<2; mt++){
            #pragma unroll
            for (int nt=0; nt<4; nt++){
                int colb = col0 + wn*32 + nt*8 + 2*(lane & 3);
                #pragma unroll
                for (int half=0; half<2; half++){
                    int row = row0 + wm*32 + mt*16 + (lane >> 2) + half*8;
                    float v0 = acc[mt][nt][half*2+0];
                    float v1 = acc[mt][nt][half*2+1];
                    if (flags & F_BIAS){ v0 += bias[colb]; v1 += bias[colb+1]; }
                    if (flags & F_FILM){
                        v0 = fmaf(v0, gamma[colb],   beta[colb]);
                        v1 = fmaf(v1, gamma[colb+1], beta[colb+1]);
                    }
                    if (flags & F_SILU){
                        v0 = v0 * __fdividef(1.f, 1.f + __expf(-v0));
                        v1 = v1 * __fdividef(1.f, 1.f + __expf(-v1));
                    }
                    size_t o = (size_t)row*Mout + colb;
                    if (flags & F_RES){
                        float2 rr = __ldcg((const float2*)&resi[o]);
                        v0 += rr.x; v1 += rr.y;
                    }
                    if (flags & F_F32){ *(float2*)&outf[o] = make_float2(v0, v1); }
                    if (flags & F_BF16){
                        bf16 h0v = __float2bfloat16(v0), h1v = __float2bfloat16(v1);
                        *(__nv_bfloat162*)&outh[o] = __halves2bfloat162(h0v, h1v);
                        *(__nv_bfloat162*)&outl[o] = __halves2bfloat162(
                            __float2bfloat16(v0 - __bfloat162float(h0v)),
                            __float2bfloat16(v1 - __bfloat162float(h1v)));
                    }
                }
            }
        }
    }
}

__device__ void gather_phase(const bf16* gh, const bf16* gl, bf16* oh, bf16* ol){
    int wid = threadIdx.x >> 5, lane = threadIdx.x & 31;
    for (int node = blockIdx.x*8 + wid; node < NPTS; node += gridDim.x*8){
        int idx = 0;
        if (lane < KNN) idx = __ldcg(&g_knn[node*KNN + lane]);
        float s0[3]={0,0,0}, s1[3]={0,0,0};
        #pragma unroll
        for (int k=0;k<KNN;k++){
            int j = __shfl_sync(0xffffffffu, idx, k);
            size_t base = (size_t)j*192 + lane*2;
            #pragma unroll
            for (int c=0;c<3;c++){
                unsigned uh = __ldcg((const unsigned*)(gh + base + 64*c));
                unsigned ul = __ldcg((const unsigned*)(gl + base + 64*c));
                float2 vh = __bfloat1622float2(*reinterpret_cast<__nv_bfloat162*>(&uh));
                float2 vl = __bfloat1622float2(*reinterpret_cast<__nv_bfloat162*>(&ul));
                s0[c] += vh.x + vl.x;
                s1[c] += vh.y + vl.y;
            }
        }
        size_t ob = (size_t)node*192 + lane*2;
        #pragma unroll
        for (int c=0;c<3;c++){
            float v0 = s0[c] * (1.0f/12.0f), v1 = s1[c] * (1.0f/12.0f);
            bf16 h0 = __float2bfloat16(v0), h1 = __float2bfloat16(v1);
            *(__nv_bfloat162*)(oh + ob + 64*c) = __halves2bfloat162(h0, h1);
            *(__nv_bfloat162*)(ol + ob + 64*c) = __halves2bfloat162(
                __float2bfloat16(v0 - __bfloat162float(h0)),
                __float2bfloat16(v1 - __bfloat162float(h1)));
        }
    }
}

__global__ void __launch_bounds__(256,2) k_net(
    const float* __restrict__ B,
    const float* __restrict__ b_in, const float* __restrict__ bg_in,
    const float* __restrict__ bg,
    const float* __restrict__ W_out, const float* __restrict__ b_out,
    float* __restrict__ out)
{
    __shared__ bf16 Ah[128][40], Al[128][40], Bh[64][40], Bl[64][40];
    int tid = threadIdx.x;
    int gen = 1;

    // ---- phase 0: fourier features + kNN (sorted space) ----
    for (int i = blockIdx.x*256 + tid; i < NPTS; i += gridDim.x*256){
        float4 p = g_spts[i];
        float f[48];
        #pragma unroll
        for (int s=0;s<3;s++){
            #pragma unroll
            for (int m=0;m<8;m++){
                float pr = p.x*B[(s*3+0)*8+m] + p.y*B[(s*3+1)*8+m] + p.z*B[(s*3+2)*8+m];
                float sv, cv; sincosf(pr, &sv, &cv);
                f[s*8+m] = sv; f[24+s*8+m] = cv;
            }
        }
        #pragma unroll
        for (int c=0;c<48;c++){
            float v = f[c];
            bf16 hv = __float2bfloat16(v);
            g_ffh[i*64+c] = hv;
            g_ffl[i*64+c] = __float2bfloat16(v - __bfloat162float(hv));
        }
        #pragma unroll
        for (int c=48;c<64;c++){
            g_ffh[i*64+c] = __float2bfloat16(0.f);
            g_ffl[i*64+c] = __float2bfloat16(0.f);
        }
    }
    for (int i = blockIdx.x*256 + tid; i < NPTS; i += gridDim.x*256){
        float4 q = g_spts[i];
        float lo[3], h[3], ih[3], qc[3];
        qc[0]=q.x; qc[1]=q.y; qc[2]=q.z;
        #pragma unroll
        for (int a=0;a<3;a++){
            lo[a] = funmap(g_bmin[a]);
            float hi = funmap(g_bmax[a]);
            h[a]  = (hi - lo[a]) * (1.0f/GD);
            ih[a] = (float)GD / (hi - lo[a]);
        }
        int cc[3];
        #pragma unroll
        for (int a=0;a<3;a++) cc[a] = min(GD-1, max(0, (int)floorf((qc[a]-lo[a])*ih[a])));

        float bd[KNN]; int bi[KNN];
        #pragma unroll
        for (int k=0;k<KNN;k++){ bd[k]=1e30f; bi[k]=0; }
        float qx2 = -2.0f*q.x, qy2 = -2.0f*q.y, qz2 = -2.0f*q.z;

        auto insert = [&](float d2, int p2){
            #pragma unroll
            for (int k=0;k<KNN;k++){
                if (d2 < bd[k]){
                    float td=bd[k]; int tp=bi[k];
                    bd[k]=d2; bi[k]=p2; d2=td; p2=tp;
                }
            }
        };
        auto visit = [&](int cell){
            int2 rc = g_cellrange[cell];
            int e = rc.x + rc.y;
            for (int j=rc.x; j<e; j++){
                float4 w = g_spts[j];
                float sc = fmaf(qx2, w.x, fmaf(qy2, w.y, fmaf(qz2, w.z, q.w + w.w)));
                if (sc < bd[KNN-1] && j != i) insert(sc, j);
            }
        };

        for (int r=0; r<GD; ++r){
            int zl = max(cc[2]-r, 0), zh = min(cc[2]+r, GD-1);
            for (int z=zl; z<=zh; ++z){
                bool ze = (z == cc[2]-r) || (z == cc[2]+r);
                int yl = max(cc[1]-r, 0), yh = min(cc[1]+r, GD-1);
                for (int y=yl; y<=yh; ++y){
                    bool ye = (y == cc[1]-r) || (y == cc[1]+r);
                    int base = (z*GD + y)*GD;
                    if (ze || ye){
                        int xl = max(cc[0]-r, 0), xh = min(cc[0]+r, GD-1);
                        for (int xx=xl; xx<=xh; ++xx) visit(base + xx);
                    } else {
                        int x1 = cc[0]-r; if (x1 >= 0) visit(base + x1);
                        int x2 = cc[0]+r; if (x2 <= GD-1 && r > 0) visit(base + x2);
                    }
                }
            }
            float dmin = 1e30f;
            #pragma unroll
            for (int a=0;a<3;a++){
                if (cc[a]-r > 0)    dmin = fminf(dmin, qc[a] - (lo[a] + (float)(cc[a]-r)*h[a]));
                if (cc[a]+r < GD-1) dmin = fminf(dmin, (lo[a] + (float)(cc[a]+r+1)*h[a]) - qc[a]);
            }
            if (dmin >= 1e29f) break;
            if (bd[KNN-1] + 1e-4f <= dmin*dmin) break;
        }
        #pragma unroll
        for (int k=0;k<KNN;k++) g_knn[i*KNN + k] = bi[k];
    }
    netbar(gen++);

    // ---- embeddings ----
    mma_layer(Ah,Al,Bh,Bl, g_ffh,g_ffl, g_Winh,g_Winl,64,
              nullptr,nullptr,nullptr,nullptr,0, 256,4,
              b_in, nullptr,nullptr, nullptr, g_h0, nullptr,nullptr, F_BIAS|F_SILU|F_F32);
    mma_layer(Ah,Al,Bh,Bl, g_ffh,g_ffl, g_Wginh,g_Wginl,64,
              nullptr,nullptr,nullptr,nullptr,0, 192,3,
              bg_in, nullptr,nullptr, nullptr, nullptr, g_gah,g_gal, F_BIAS|F_SILU|F_BF16);
    netbar(gen++);

    // ---- graph message passing ----
    bf16 *gch=g_gah, *gcl=g_gal, *gnh=g_gbh, *gnl=g_gbl;
    for (int l=0; l<4; l++){
        gather_phase(gch, gcl, g_aggh, g_aggl);
        netbar(gen++);
        mma_layer(Ah,Al,Bh,Bl, gch,gcl, g_Wsh+l*192*192, g_Wsl+l*192*192, 192,
                  g_aggh,g_aggl, g_Wnh+l*192*192, g_Wnl+l*192*192, 192, 192,3,
                  bg + l*192, nullptr,nullptr, nullptr, nullptr, gnh,gnl, F_BIAS|F_SILU|F_BF16);
        netbar(gen++);
        bf16* t;
        t=gch; gch=gnh; gnh=t;  t=gcl; gcl=gnl; gnl=t;
    }

    // ---- inject graph context ----
    mma_layer(Ah,Al,Bh,Bl, gch,gcl, g_Wgoh,g_Wgol,192,
              nullptr,nullptr,nullptr,nullptr,0, 256,4,
              nullptr, nullptr,nullptr, g_h0, nullptr, g_hah,g_hal, F_RES|F_BF16);
    netbar(gen++);

    // ---- FiLM trunk ----
    bf16 *hch=g_hah, *hcl=g_hal, *hnh=g_hbh, *hnl=g_hbl;
    for (int l=0; l<7; l++){
        int flags = F_FILM|F_SILU;
        const float* res = nullptr;
        if (l == 2 || l == 5){ flags |= F_RES; res = g_h0; }
        float* of = nullptr;
        bf16 *oh = hnh, *ol = hnl;
        if (l == 6){ flags |= F_F32; of = g_hf; oh = nullptr; ol = nullptr; }
        else flags |= F_BF16;
        mma_layer(Ah,Al,Bh,Bl, hch,hcl, g_Wh+l*256*256, g_Wl+l*256*256, 256,
                  nullptr,nullptr,nullptr,nullptr,0, 256,4,
                  nullptr, g_film+l*512, g_film+l*512+256, res, of, oh, ol, flags);
        netbar(gen++);
        bf16* t;
        t=hch; hch=hnh; hnh=t;  t=hcl; hcl=hnl; hnl=t;
    }

    // ---- output projection ----
    for (int i = blockIdx.x*256 + tid; i < NPTS; i += gridDim.x*256){
        const float* hr = g_hf + (size_t)i*256;
        float a0=0.f, a1=0.f, a2=0.f;
        #pragma unroll 8
        for (int k=0;k<256;k++){
            float hv = __ldcg(hr + k);
            a0 = fmaf(hv, W_out[k*3+0], a0);
            a1 = fmaf(hv, W_out[k*3+1], a1);
            a2 = fmaf(hv, W_out[k*3+2], a2);
        }
        int orig = g_sorted[i];
        out[orig*3+0] = (a0 + b_out[0]) * 0.01f;
        out[orig*3+1] = (a1 + b_out[1]) * 0.01f;
        out[orig*3+2] = (a2 + b_out[2]) * 0.01f;
    }
}

// ================= launch =================
extern "C" void kernel_launch(void* const* d_in, const int* in_sizes, int n_in,
                              void* d_out, int out_size)
{
    const float* x      = (const float*)d_in[0];
    const float* cond   = (const float*)d_in[1];
    const float* B      = (const float*)d_in[2];
    const float* W_in   = (const float*)d_in[3];
    const float* b_in   = (const float*)d_in[4];
    const float* Wg_in  = (const float*)d_in[5];
    const float* bg_in  = (const float*)d_in[6];
    const float* Ws     = (const float*)d_in[7];
    const float* Wn     = (const float*)d_in[8];
    const float* bg     = (const float*)d_in[9];
    const float* Wg_out = (const float*)d_in[10];
    const float* W      = (const float*)d_in[11];
    const float* bmlp   = (const float*)d_in[12];
    const float* Wf_g   = (const float*)d_in[13];
    const float* bf_g   = (const float*)d_in[14];
    const float* Wf_b   = (const float*)d_in[15];
    const float* bf_b   = (const float*)d_in[16];
    const float* W_out  = (const float*)d_in[17];
    const float* b_out  = (const float*)d_in[18];
    float* out = (float*)d_out;

    k_init_prep   <<<2048, 256>>>(x, W_in, Wg_in, Ws, Wn, Wg_out, W,
                                  cond, Wf_g, bf_g, Wf_b, bf_b, bmlp);
    k_cell        <<<NPTS/256, 256>>>();
    k_scan_scatter<<<512, 512>>>();
    k_net         <<<NETB, 256>>>(B, b_in, bg_in, bg, W_out, b_out, out);
}

// round 9
// speedup vs baseline: 1.2099x; 1.2099x over previous
#include <cuda_runtime.h>
#include <cuda_bf16.h>
#include <cstdint>
#include <math.h>

#define NPTS 65536
#define GD   64
#define G3   (GD*GD*GD)
#define KNN  12

// ================= mma.sync helpers (family-agnostic HMMA path) =================
__device__ __forceinline__ uint32_t smem_to_u32(const void* p){
    uint32_t a;
    asm("{ .reg .u64 t; cvta.to.shared.u64 t, %1; cvt.u32.u64 %0, t; }" : "=r"(a) : "l"(p));
    return a;
}
__device__ __forceinline__ void ldsm4(uint32_t& r0,uint32_t& r1,uint32_t& r2,uint32_t& r3,uint32_t addr){
    asm volatile("ldmatrix.sync.aligned.m8n8.x4.shared.b16 {%0,%1,%2,%3},[%4];"
        : "=r"(r0),"=r"(r1),"=r"(r2),"=r"(r3) : "r"(addr));
}
__device__ __forceinline__ void ldsm2(uint32_t& r0,uint32_t& r1,uint32_t addr){
    asm volatile("ldmatrix.sync.aligned.m8n8.x2.shared.b16 {%0,%1},[%2];"
        : "=r"(r0),"=r"(r1) : "r"(addr));
}
__device__ __forceinline__ void mma16816(float* c, const uint32_t* a, const uint32_t* b){
    asm volatile("mma.sync.aligned.m16n8k16.row.col.f32.bf16.bf16.f32 "
        "{%0,%1,%2,%3},{%4,%5,%6,%7},{%8,%9},{%0,%1,%2,%3};"
        : "+f"(c[0]),"+f"(c[1]),"+f"(c[2]),"+f"(c[3])
        : "r"(a[0]),"r"(a[1]),"r"(a[2]),"r"(a[3]), "r"(b[0]),"r"(b[1]));
}

// ================= scratch =================
__device__ float4        g_pts[NPTS];
__device__ float4        g_spts[NPTS];          // cell-sorted
__device__ int           g_sorted[NPTS];        // pos -> orig
__device__ int           g_knn[NPTS*KNN];       // sorted-space indices
__device__ int           g_cellcount[G3];
__device__ int           g_cellstart[G3];
__device__ int2          g_cellrange[G3];
__device__ int           g_cellfill[G3];
__device__ int           g_cellof[NPTS];
__device__ unsigned      g_bmin[3];
__device__ unsigned      g_bmax[3];
__device__ int           g_bsum[256];
__device__ int           g_bsum2[256];
__device__ float         g_film[7*512];
__device__ __nv_bfloat16 g_ffh[NPTS*64],  g_ffl[NPTS*64];
__device__ __nv_bfloat16 g_gah[NPTS*192], g_gal[NPTS*192];
__device__ __nv_bfloat16 g_gbh[NPTS*192], g_gbl[NPTS*192];
__device__ __nv_bfloat16 g_aggh[NPTS*192],g_aggl[NPTS*192];
__device__ __nv_bfloat16 g_hah[NPTS*256], g_hal[NPTS*256];
__device__ __nv_bfloat16 g_hbh[NPTS*256], g_hbl[NPTS*256];
__device__ float         g_h0[NPTS*256];
__device__ float         g_hf[NPTS*256];

__device__ __forceinline__ unsigned fmap(float x){
    unsigned u = __float_as_uint(x);
    return (u & 0x80000000u) ? ~u : (u | 0x80000000u);
}
__device__ __forceinline__ float funmap(unsigned u){
    return (u & 0x80000000u) ? __uint_as_float(u & 0x7FFFFFFFu) : __uint_as_float(~u);
}

// ================= graph build (identical to R4 best) =================
__global__ void k_init(){
    int i = blockIdx.x*blockDim.x + threadIdx.x;
    if (i < G3){ g_cellcount[i]=0; g_cellfill[i]=0; }
    if (i < 3){ g_bmin[i]=0xFFFFFFFFu; g_bmax[i]=0u; }
}

__global__ void k_prep(const float* __restrict__ x){
    int i = blockIdx.x*blockDim.x + threadIdx.x;
    float x0=x[i*3+0], x1=x[i*3+1], x2=x[i*3+2];
    g_pts[i] = make_float4(x0,x1,x2, x0*x0+x1*x1+x2*x2);
    float mn0=x0, mn1=x1, mn2=x2, mx0=x0, mx1=x1, mx2=x2;
    #pragma unroll
    for (int o=16;o>0;o>>=1){
        mn0=fminf(mn0,__shfl_down_sync(0xffffffffu,mn0,o));
        mn1=fminf(mn1,__shfl_down_sync(0xffffffffu,mn1,o));
        mn2=fminf(mn2,__shfl_down_sync(0xffffffffu,mn2,o));
        mx0=fmaxf(mx0,__shfl_down_sync(0xffffffffu,mx0,o));
        mx1=fmaxf(mx1,__shfl_down_sync(0xffffffffu,mx1,o));
        mx2=fmaxf(mx2,__shfl_down_sync(0xffffffffu,mx2,o));
    }
    if ((threadIdx.x & 31) == 0){
        atomicMin(&g_bmin[0], fmap(mn0)); atomicMax(&g_bmax[0], fmap(mx0));
        atomicMin(&g_bmin[1], fmap(mn1)); atomicMax(&g_bmax[1], fmap(mx1));
        atomicMin(&g_bmin[2], fmap(mn2)); atomicMax(&g_bmax[2], fmap(mx2));
    }
}

__global__ void k_cell(){
    int i = blockIdx.x*blockDim.x + threadIdx.x;
    float4 p = g_pts[i];
    float lo0=funmap(g_bmin[0]), lo1=funmap(g_bmin[1]), lo2=funmap(g_bmin[2]);
    float ih0 = (float)GD / (funmap(g_bmax[0]) - lo0);
    float ih1 = (float)GD / (funmap(g_bmax[1]) - lo1);
    float ih2 = (float)GD / (funmap(g_bmax[2]) - lo2);
    int cx = min(GD-1, max(0, (int)floorf((p.x - lo0)*ih0)));
    int cy = min(GD-1, max(0, (int)floorf((p.y - lo1)*ih1)));
    int cz = min(GD-1, max(0, (int)floorf((p.z - lo2)*ih2)));
    int c = (cz*GD + cy)*GD + cx;
    g_cellof[i] = c;
    atomicAdd(&g_cellcount[c], 1);
}

__global__ void k_scan1(){
    __shared__ int s[1024];
    int gid = blockIdx.x*1024 + threadIdx.x;
    int v = g_cellcount[gid];
    s[threadIdx.x] = v; __syncthreads();
    for (int off=1; off<1024; off<<=1){
        int t = (threadIdx.x >= off) ? s[threadIdx.x-off] : 0;
        __syncthreads(); s[threadIdx.x] += t; __syncthreads();
    }
    g_cellstart[gid] = s[threadIdx.x] - v;
    if (threadIdx.x == 1023) g_bsum[blockIdx.x] = s[1023];
}
__global__ void k_scan2(){
    __shared__ int s[256];
    int v = g_bsum[threadIdx.x];
    s[threadIdx.x] = v; __syncthreads();
    for (int off=1; off<256; off<<=1){
        int t = (threadIdx.x >= off) ? s[threadIdx.x-off] : 0;
        __syncthreads(); s[threadIdx.x] += t; __syncthreads();
    }
    g_bsum2[threadIdx.x] = s[threadIdx.x] - v;
}
__global__ void k_scan3(){
    int gid = blockIdx.x*1024 + threadIdx.x;
    int st = g_cellstart[gid] + g_bsum2[blockIdx.x];
    g_cellstart[gid] = st;
    g_cellrange[gid] = make_int2(st, g_cellcount[gid]);
}

__global__ void k_scatter(){
    int i = blockIdx.x*blockDim.x + threadIdx.x;
    int c = g_cellof[i];
    int pos = g_cellstart[c] + atomicAdd(&g_cellfill[c], 1);
    g_sorted[pos] = i;
    g_spts[pos]  = g_pts[i];
}

// fourier features in sorted order -> bf16 hi/lo, padded to 64 cols
__global__ void k_ff(const float* __restrict__ B){
    int i = blockIdx.x*blockDim.x + threadIdx.x;
    float4 p = g_spts[i];
    float f[48];
    #pragma unroll
    for (int s=0;s<3;s++){
        #pragma unroll
        for (int m=0;m<8;m++){
            float pr = p.x*B[(s*3+0)*8+m] + p.y*B[(s*3+1)*8+m] + p.z*B[(s*3+2)*8+m];
            float sv, cv; sincosf(pr, &sv, &cv);
            f[s*8+m] = sv; f[24+s*8+m] = cv;
        }
    }
    #pragma unroll
    for (int c=0;c<48;c++){
        float v = f[c];
        __nv_bfloat16 hv = __float2bfloat16(v);
        g_ffh[i*64+c] = hv;
        g_ffl[i*64+c] = __float2bfloat16(v - __bfloat162float(hv));
    }
    #pragma unroll
    for (int c=48;c<64;c++){
        g_ffh[i*64+c] = __float2bfloat16(0.f);
        g_ffl[i*64+c] = __float2bfloat16(0.f);
    }
}

// ======= exact kNN: per-thread expanding shells (R4 version) =======
__global__ void k_knn(){
    int i = blockIdx.x*blockDim.x + threadIdx.x;   // sorted position
    float4 q = g_spts[i];
    float lo[3], h[3], ih[3], qc[3];
    qc[0]=q.x; qc[1]=q.y; qc[2]=q.z;
    #pragma unroll
    for (int a=0;a<3;a++){
        lo[a] = funmap(g_bmin[a]);
        float hi = funmap(g_bmax[a]);
        h[a]  = (hi - lo[a]) * (1.0f/GD);
        ih[a] = (float)GD / (hi - lo[a]);
    }
    int cc[3];
    #pragma unroll
    for (int a=0;a<3;a++) cc[a] = min(GD-1, max(0, (int)floorf((qc[a]-lo[a])*ih[a])));

    float bd[KNN]; int bi[KNN];
    #pragma unroll
    for (int k=0;k<KNN;k++){ bd[k]=1e30f; bi[k]=0; }
    float qx2 = -2.0f*q.x, qy2 = -2.0f*q.y, qz2 = -2.0f*q.z;

    auto visit = [&](int cell){
        int2 rc = g_cellrange[cell];
        int e = rc.x + rc.y;
        for (int j=rc.x; j<e; j++){
            float4 w = g_spts[j];
            float sc = fmaf(qx2, w.x, fmaf(qy2, w.y, fmaf(qz2, w.z, q.w + w.w)));
            if (sc < bd[KNN-1] && j != i){
                float d2 = sc; int p2 = j;
                #pragma unroll
                for (int k=0;k<KNN;k++){
                    if (d2 < bd[k]){
                        float td=bd[k]; int tp=bi[k];
                        bd[k]=d2; bi[k]=p2; d2=td; p2=tp;
                    }
                }
            }
        }
    };

    for (int r=0; r<GD; ++r){
        int zl = max(cc[2]-r, 0), zh = min(cc[2]+r, GD-1);
        for (int z=zl; z<=zh; ++z){
            bool ze = (z == cc[2]-r) || (z == cc[2]+r);
            int yl = max(cc[1]-r, 0), yh = min(cc[1]+r, GD-1);
            for (int y=yl; y<=yh; ++y){
                bool ye = (y == cc[1]-r) || (y == cc[1]+r);
                int base = (z*GD + y)*GD;
                if (ze || ye){
                    int xl = max(cc[0]-r, 0), xh = min(cc[0]+r, GD-1);
                    for (int xx=xl; xx<=xh; ++xx) visit(base + xx);
                } else {
                    int x1 = cc[0]-r; if (x1 >= 0) visit(base + x1);
                    int x2 = cc[0]+r; if (x2 <= GD-1 && r > 0) visit(base + x2);
                }
            }
        }
        float dmin = 1e30f;
        #pragma unroll
        for (int a=0;a<3;a++){
            if (cc[a]-r > 0)    dmin = fminf(dmin, qc[a] - (lo[a] + (float)(cc[a]-r)*h[a]));
            if (cc[a]+r < GD-1) dmin = fminf(dmin, (lo[a] + (float)(cc[a]+r+1)*h[a]) - qc[a]);
        }
        if (dmin >= 1e29f) break;
        if (bd[KNN-1] + 1e-4f <= dmin*dmin) break;
    }
    #pragma unroll
    for (int k=0;k<KNN;k++) g_knn[i*KNN + k] = bi[k];
}

// neighbor mean gather (R4 version), warp per node
__global__ void k_gather(const __nv_bfloat16* __restrict__ gh, const __nv_bfloat16* __restrict__ gl,
                         __nv_bfloat16* __restrict__ oh, __nv_bfloat16* __restrict__ ol){
    int gt   = blockIdx.x*blockDim.x + threadIdx.x;
    int node = gt >> 5;
    int lane = threadIdx.x & 31;
    int idx = 0;
    if (lane < KNN) idx = g_knn[node*KNN + lane];
    float s[6] = {0.f,0.f,0.f,0.f,0.f,0.f};
    #pragma unroll
    for (int k=0;k<KNN;k++){
        int j = __shfl_sync(0xffffffffu, idx, k);
        size_t base = (size_t)j*192;
        #pragma unroll
        for (int c=0;c<6;c++){
            int col = lane + 32*c;
            s[c] += __bfloat162float(gh[base+col]) + __bfloat162float(gl[base+col]);
        }
    }
    size_t ob = (size_t)node*192;
    #pragma unroll
    for (int c=0;c<6;c++){
        float v = s[c] * (1.0f/12.0f);
        int col = lane + 32*c;
        __nv_bfloat16 hv = __float2bfloat16(v);
        oh[ob+col] = hv;
        ol[ob+col] = __float2bfloat16(v - __bfloat162float(hv));
    }
}

__global__ void k_film(const float* __restrict__ cond, const float* __restrict__ Wg,
                       const float* __restrict__ bgf, const float* __restrict__ Wb,
                       const float* __restrict__ bbf){
    int l = blockIdx.x, j = threadIdx.x;
    float ga = bgf[l*256 + j], ba = bbf[l*256 + j];
    for (int k=0;k<64;k++){
        float cv = cond[k];
        ga = fmaf(cv, Wg[(l*64+k)*256 + j], ga);
        ba = fmaf(cv, Wb[(l*64+k)*256 + j], ba);
    }
    g_film[l*512 + j]       = ga;
    g_film[l*512 + 256 + j] = ba;
}

// ================= HMMA bf16x3 GEMM — double-buffered pipeline =================
#define F_BIAS 1
#define F_FILM 2
#define F_SILU 4
#define F_RES  8
#define F_F32  16
#define F_BF16 32

// per-buffer smem layout (bf16 elems): Ah 0..5119 | Al 5120..10239 | Bh 10240..12799 | Bl 12800..15359
#define SBUF  15360
#define SBYTES (2*SBUF*2)

__global__ void __launch_bounds__(256) k_mma(
    const __nv_bfloat16* __restrict__ a1h, const __nv_bfloat16* __restrict__ a1l,
    const float* __restrict__ W1, int kspan1, int kvalid1,
    const __nv_bfloat16* __restrict__ a2h, const __nv_bfloat16* __restrict__ a2l,
    const float* __restrict__ W2, int kspan2,
    int Mout,
    const float* __restrict__ bias, const float* __restrict__ gamma,
    const float* __restrict__ beta, const float* __restrict__ resi,
    float* __restrict__ outf, __nv_bfloat16* __restrict__ outh, __nv_bfloat16* __restrict__ outl,
    int flags)
{
    extern __shared__ __nv_bfloat16 sm[];

    int tid = threadIdx.x, wid = tid>>5, lane = tid&31;
    int wm = wid & 3, wn = wid >> 2;
    int row0 = blockIdx.y*128, col0 = blockIdx.x*64;

    float acc[2][4][4];
    #pragma unroll
    for (int mt=0;mt<2;mt++)
        #pragma unroll
        for (int nt=0;nt<4;nt++)
            #pragma unroll
            for (int e=0;e<4;e++) acc[mt][nt][e]=0.f;

    uint32_t smb = smem_to_u32(sm);
    uint32_t aAh = smb + (uint32_t)((wm*32 + (lane & 15))*40 + (lane >> 4)*8) * 2u;
    uint32_t aAl = aAh + 5120u*2u;
    uint32_t aBh = smb + (uint32_t)(10240 + (wn*32 + (lane & 7))*40 + ((lane >> 3) & 1)*8) * 2u;
    uint32_t aBl = aBh + 2560u*2u;

    const int ar = tid >> 3;           // A row base (0..31), +32*it
    const int ag = (tid & 7) * 4;      // A k-offset
    const int bn = tid & 63;           // B n index
    const int bk = tid >> 6;           // B k base (0..3), +4*it

    uint2 pah[4], pal[4];
    float pb[8];

    int nchunk = (kspan1 + kspan2) >> 5;

    auto ldt = [&](int c){
        int kg = c<<5;
        const __nv_bfloat16 *ah, *al; const float* Wp; int span, kv, koff;
        if (kg < kspan1){ ah=a1h; al=a1l; Wp=W1; span=kspan1; kv=kvalid1; koff=kg; }
        else            { ah=a2h; al=a2l; Wp=W2; span=kspan2; kv=kspan2; koff=kg-kspan1; }
        #pragma unroll
        for (int it=0; it<4; it++){
            size_t s = (size_t)(row0 + ar + it*32)*span + koff + ag;
            pah[it] = *(const uint2*)(ah + s);
            pal[it] = *(const uint2*)(al + s);
        }
        #pragma unroll
        for (int it=0; it<8; it++){
            int k0 = koff + bk + it*4;
            pb[it] = (k0 < kv) ? Wp[(size_t)k0*Mout + col0 + bn] : 0.f;
        }
    };
    auto stt = [&](int buf){
        __nv_bfloat16* base = sm + buf*SBUF;
        #pragma unroll
        for (int it=0; it<4; it++){
            int r = ar + it*32;
            *(uint2*)(base + r*40 + ag)        = pah[it];
            *(uint2*)(base + 5120 + r*40 + ag) = pal[it];
        }
        #pragma unroll
        for (int it=0; it<8; it++){
            float w = pb[it];
            __nv_bfloat16 hb = __float2bfloat16(w);
            base[10240 + bn*40 + bk + it*4] = hb;
            base[12800 + bn*40 + bk + it*4] = __float2bfloat16(w - __bfloat162float(hb));
        }
    };

    ldt(0); stt(0); __syncthreads();

    for (int c=0; c<nchunk; c++){
        int buf = c & 1;
        if (c+1 < nchunk) ldt(c+1);
        uint32_t boff = (uint32_t)buf * (uint32_t)(SBUF*2);

        #pragma unroll
        for (int ks=0; ks<2; ks++){
            uint32_t afh[2][4], afl[2][4], bfh[4][2], bfl[4][2];
            #pragma unroll
            for (int mt=0; mt<2; mt++){
                uint32_t off = boff + (uint32_t)(mt*16*40 + ks*16) * 2u;
                ldsm4(afh[mt][0],afh[mt][1],afh[mt][2],afh[mt][3], aAh + off);
                ldsm4(afl[mt][0],afl[mt][1],afl[mt][2],afl[mt][3], aAl + off);
            }
            #pragma unroll
            for (int nt=0; nt<4; nt++){
                uint32_t off = boff + (uint32_t)(nt*8*40 + ks*16) * 2u;
                ldsm2(bfh[nt][0],bfh[nt][1], aBh + off);
                ldsm2(bfl[nt][0],bfl[nt][1], aBl + off);
            }
            #pragma unroll
            for (int mt=0; mt<2; mt++)
                #pragma unroll
                for (int nt=0; nt<4; nt++){
                    mma16816(acc[mt][nt], afh[mt], bfh[nt]);
                    mma16816(acc[mt][nt], afh[mt], bfl[nt]);
                    mma16816(acc[mt][nt], afl[mt], bfh[nt]);
                }
        }
        if (c+1 < nchunk){ stt(buf^1); __syncthreads(); }
    }

    #pragma unroll
    for (int mt=0; mt<2; mt++){
        #pragma unroll
        for (int nt=0; nt<4; nt++){
            int colb = col0 + wn*32 + nt*8 + 2*(lane & 3);
            #pragma unroll
            for (int half=0; half<2; half++){
                int row = row0 + wm*32 + mt*16 + (lane >> 2) + half*8;
                float v0 = acc[mt][nt][half*2+0];
                float v1 = acc[mt][nt][half*2+1];
                if (flags & F_BIAS){ v0 += bias[colb]; v1 += bias[colb+1]; }
                if (flags & F_FILM){
                    v0 = fmaf(v0, 1.f + gamma[colb],   beta[colb]);
                    v1 = fmaf(v1, 1.f + gamma[colb+1], beta[colb+1]);
                }
                if (flags & F_SILU){
                    v0 = v0 * __fdividef(1.f, 1.f + __expf(-v0));
                    v1 = v1 * __fdividef(1.f, 1.f + __expf(-v1));
                }
                size_t o = (size_t)row*Mout + colb;
                if (flags & F_RES){ v0 += resi[o]; v1 += resi[o+1]; }
                if (flags & F_F32){ *(float2*)&outf[o] = make_float2(v0, v1); }
                if (flags & F_BF16){
                    __nv_bfloat16 h0 = __float2bfloat16(v0), h1 = __float2bfloat16(v1);
                    *(__nv_bfloat162*)&outh[o] = __halves2bfloat162(h0, h1);
                    *(__nv_bfloat162*)&outl[o] = __halves2bfloat162(
                        __float2bfloat16(v0 - __bfloat162float(h0)),
                        __float2bfloat16(v1 - __bfloat162float(h1)));
                }
            }
        }
    }
}

// ================= output projection (warp per node, coalesced) =================
__global__ void k_out(const float* __restrict__ h, const float* __restrict__ Wout,
                      const float* __restrict__ bout, float* __restrict__ out){
    int gt = blockIdx.x*blockDim.x + threadIdx.x;
    int node = gt >> 5;
    int lane = threadIdx.x & 31;
    const float* hr = h + (size_t)node*256;
    float a0=0.f, a1=0.f, a2=0.f;
    #pragma unroll
    for (int k0=0; k0<8; k0++){
        int k = k0*32 + lane;
        float hv = hr[k];
        a0 = fmaf(hv, Wout[k*3+0], a0);
        a1 = fmaf(hv, Wout[k*3+1], a1);
        a2 = fmaf(hv, Wout[k*3+2], a2);
    }
    #pragma unroll
    for (int o=16;o>0;o>>=1){
        a0 += __shfl_down_sync(0xffffffffu, a0, o);
        a1 += __shfl_down_sync(0xffffffffu, a1, o);
        a2 += __shfl_down_sync(0xffffffffu, a2, o);
    }
    if (lane == 0){
        int orig = g_sorted[node];
        out[orig*3+0] = (a0 + bout[0]) * 0.01f;
        out[orig*3+1] = (a1 + bout[1]) * 0.01f;
        out[orig*3+2] = (a2 + bout[2]) * 0.01f;
    }
}

// ================= launch =================
extern "C" void kernel_launch(void* const* d_in, const int* in_sizes, int n_in,
                              void* d_out, int out_size)
{
    const float* x      = (const float*)d_in[0];
    const float* cond   = (const float*)d_in[1];
    const float* B      = (const float*)d_in[2];
    const float* W_in   = (const float*)d_in[3];
    const float* b_in   = (const float*)d_in[4];
    const float* Wg_in  = (const float*)d_in[5];
    const float* bg_in  = (const float*)d_in[6];
    const float* Ws     = (const float*)d_in[7];
    const float* Wn     = (const float*)d_in[8];
    const float* bg     = (const float*)d_in[9];
    const float* Wg_out = (const float*)d_in[10];
    const float* W      = (const float*)d_in[11];
    const float* bmlp   = (const float*)d_in[12];
    const float* Wf_g   = (const float*)d_in[13];
    const float* bf_g   = (const float*)d_in[14];
    const float* Wf_b   = (const float*)d_in[15];
    const float* bf_b   = (const float*)d_in[16];
    const float* W_out  = (const float*)d_in[17];
    const float* b_out  = (const float*)d_in[18];
    float* out = (float*)d_out;

    cudaFuncSetAttribute(k_mma, cudaFuncAttributeMaxDynamicSharedMemorySize, SBYTES);

    float *p_h0,*p_hf,*p_film;
    __nv_bfloat16 *p_ffh,*p_ffl,*p_gah,*p_gal,*p_gbh,*p_gbl,*p_aggh,*p_aggl,*p_hah,*p_hal,*p_hbh,*p_hbl;
    cudaGetSymbolAddress((void**)&p_h0,  g_h0);
    cudaGetSymbolAddress((void**)&p_hf,  g_hf);
    cudaGetSymbolAddress((void**)&p_film,g_film);
    cudaGetSymbolAddress((void**)&p_ffh, g_ffh);  cudaGetSymbolAddress((void**)&p_ffl, g_ffl);
    cudaGetSymbolAddress((void**)&p_gah, g_gah);  cudaGetSymbolAddress((void**)&p_gal, g_gal);
    cudaGetSymbolAddress((void**)&p_gbh, g_gbh);  cudaGetSymbolAddress((void**)&p_gbl, g_gbl);
    cudaGetSymbolAddress((void**)&p_aggh,g_aggh); cudaGetSymbolAddress((void**)&p_aggl,g_aggl);
    cudaGetSymbolAddress((void**)&p_hah, g_hah);  cudaGetSymbolAddress((void**)&p_hal, g_hal);
    cudaGetSymbolAddress((void**)&p_hbh, g_hbh);  cudaGetSymbolAddress((void**)&p_hbl, g_hbl);

    // graph build (sorted space) — R4 structure
    k_init   <<<G3/256, 256>>>();
    k_prep   <<<NPTS/256, 256>>>(x);
    k_cell   <<<NPTS/256, 256>>>();
    k_scan1  <<<256, 1024>>>();
    k_scan2  <<<1, 256>>>();
    k_scan3  <<<256, 1024>>>();
    k_scatter<<<NPTS/256, 256>>>();
    k_ff     <<<NPTS/256, 256>>>(B);
    k_knn    <<<NPTS/256, 256>>>();
    k_film   <<<7, 256>>>(cond, Wf_g, bf_g, Wf_b, bf_b);

    // h0 = silu(ff @ W_in + b_in)   (fp32, used for residuals)
    k_mma<<<dim3(4,512), 256, SBYTES>>>(p_ffh, p_ffl, W_in, 64, 48,
        nullptr, nullptr, nullptr, 0, 256,
        b_in, nullptr, nullptr, nullptr, p_h0, nullptr, nullptr, F_BIAS|F_SILU|F_F32);
    // gfeat = silu(ff @ Wg_in + bg_in)
    k_mma<<<dim3(3,512), 256, SBYTES>>>(p_ffh, p_ffl, Wg_in, 64, 48,
        nullptr, nullptr, nullptr, 0, 192,
        bg_in, nullptr, nullptr, nullptr, nullptr, p_gah, p_gal, F_BIAS|F_SILU|F_BF16);

    // graph message passing
    __nv_bfloat16 *gch=p_gah, *gcl=p_gal, *gnh=p_gbh, *gnl=p_gbl;
    for (int l=0; l<4; l++){
        k_gather<<<NPTS*32/256, 256>>>(gch, gcl, p_aggh, p_aggl);
        k_mma<<<dim3(3,512), 256, SBYTES>>>(gch, gcl, Ws + l*192*192, 192, 192,
            p_aggh, p_aggl, Wn + l*192*192, 192, 192,
            bg + l*192, nullptr, nullptr, nullptr, nullptr, gnh, gnl, F_BIAS|F_SILU|F_BF16);
        __nv_bfloat16* t;
        t=gch; gch=gnh; gnh=t;  t=gcl; gcl=gnl; gnl=t;
    }

    // h = h0 + gfeat @ Wg_out
    k_mma<<<dim3(4,512), 256, SBYTES>>>(gch, gcl, Wg_out, 192, 192,
        nullptr, nullptr, nullptr, 0, 256,
        nullptr, nullptr, nullptr, p_h0, nullptr, p_hah, p_hal, F_RES|F_BF16);

    // FiLM trunk
    __nv_bfloat16 *hch=p_hah, *hcl=p_hal, *hnh=p_hbh, *hnl=p_hbl;
    for (int l=0; l<7; l++){
        int flags = F_BIAS|F_FILM|F_SILU;
        const float* res = nullptr;
        if (l == 2 || l == 5){ flags |= F_RES; res = p_h0; }
        float* of = nullptr;
        __nv_bfloat16 *oh = hnh, *ol = hnl;
        if (l == 6){ flags |= F_F32; of = p_hf; oh = nullptr; ol = nullptr; }
        else flags |= F_BF16;
        k_mma<<<dim3(4,512), 256, SBYTES>>>(hch, hcl, W + l*256*256, 256, 256,
            nullptr, nullptr, nullptr, 0, 256,
            bmlp + l*256, p_film + l*512, p_film + l*512 + 256,
            res, of, oh, ol, flags);
        __nv_bfloat16* t;
        t=hch; hch=hnh; hnh=t;  t=hcl; hcl=hnl; hnl=t;
    }

    k_out<<<NPTS*32/256, 256>>>(p_hf, W_out, b_out, out);
}